// round 16
// baseline (speedup 1.0000x reference)
#include <cuda_runtime.h>
#include <cstdint>
#include <cstddef>

#define TT   2048
#define BB   64
#define NIN  128
#define HH   256
#define NOUT 128
#define MROWS (TT * BB)   // 131072

__device__ __align__(16) float g_xp[(size_t)TT * BB * HH];  // 128 MB
__device__ __align__(16) float g_hs[(size_t)TT * BB * HH];  // 128 MB

__device__ __forceinline__ unsigned long long fma2(unsigned long long a,
                                                   unsigned long long b,
                                                   unsigned long long c) {
    unsigned long long d;
    asm("fma.rn.f32x2 %0, %1, %2, %3;" : "=l"(d) : "l"(a), "l"(b), "l"(c));
    return d;
}
__device__ __forceinline__ float red2(unsigned long long a) {
    float lo, hi;
    asm("mov.b64 {%0, %1}, %2;" : "=f"(lo), "=f"(hi) : "l"(a));
    return lo + hi;
}
__device__ __forceinline__ uint32_t smem_u32(const void* p) {
    uint32_t a;
    asm("{ .reg .u64 t; cvta.to.shared.u64 t, %1; cvt.u32.u64 %0, t; }" : "=r"(a) : "l"(p));
    return a;
}
__device__ __forceinline__ uint32_t mapa_u32(uint32_t addr, uint32_t rank) {
    uint32_t r;
    asm("mapa.shared::cluster.u32 %0, %1, %2;" : "=r"(r) : "r"(addr), "r"(rank));
    return r;
}
__device__ __forceinline__ void cluster_sync_() {
    asm volatile("barrier.cluster.arrive.aligned;" ::: "memory");
    asm volatile("barrier.cluster.wait.aligned;" ::: "memory");
}
// producer/consumer named barriers
__device__ __forceinline__ void nbar_sync(int id) {
    asm volatile("bar.sync %0, 256;" :: "r"(id) : "memory");
}
__device__ __forceinline__ void nbar_arrive(int id) {
    asm volatile("bar.arrive %0, 256;" :: "r"(id) : "memory");
}
__device__ __forceinline__ void nbar_sync_g1() {       // g1-only (128 threads)
    asm volatile("bar.sync 3, 128;" ::: "memory");
}
// ---- tagged-slot DSMEM exchange (plain path, no async proxy) ----
// sender: one atomic 8B store {h, tag} into the peer's slot
__device__ __forceinline__ void st_slot(uint32_t addr, float h, uint32_t tag) {
    unsigned long long v;
    asm("mov.b64 %0, {%1, %2};" : "=l"(v) : "r"(__float_as_uint(h)), "r"(tag));
    asm volatile("st.relaxed.cluster.shared::cluster.b64 [%0], %1;"
                 :: "r"(addr), "l"(v) : "memory");
}
// receiver: spin on OWN local slot until tag matches; returns h
__device__ __forceinline__ float poll_slot(uint32_t addr, uint32_t exp) {
    unsigned long long v;
    uint32_t lo, hi;
    do {
        asm volatile("ld.relaxed.cluster.shared::cta.b64 %0, [%1];"
                     : "=l"(v) : "r"(addr) : "memory");
        asm("mov.b64 {%0, %1}, %2;" : "=r"(lo), "=r"(hi) : "l"(v));
    } while (hi != exp);
    return __uint_as_float(lo);
}
// tanh(x) = 1 - 2/(exp(2x)+1), MUFU-based (~45 cyc)
__device__ __forceinline__ float fast_tanh(float x) {
    float e, r;
    float t = x * 2.8853900817779268f;      // 2*log2(e)
    asm("ex2.approx.f32 %0, %1;" : "=f"(e) : "f"(t));
    float d = e + 1.0f;
    asm("rcp.approx.f32 %0, %1;" : "=f"(r) : "f"(d));
    return fmaf(-2.0f, r, 1.0f);
}

// dummy pad kernel — keeps k_scan at the profiled launch index
__global__ void k_nop() {}

// =====================================================================
// K1/K3 unified projection (R8 version — measured best)
// =====================================================================
template<int O, int K, bool TWOB>
__global__ void __launch_bounds__(512, 1)
k_proj(const float* __restrict__ A, const float* __restrict__ W,
       const float* __restrict__ bias1, const float* __restrict__ bias2,
       float* __restrict__ C) {
    constexpr int G   = 512 / O;
    constexpr int KT  = K / G;       // 64
    constexpr int KT4 = KT / 4;      // 16
    constexpr int RPB = 64;
    constexpr int RG  = 8;
    constexpr int NGR = RPB / RG;
    constexpr int NLD = RG * K / 4;

    __shared__ __align__(16) float stage[2][RG * K];
    __shared__ float scr[2][G - 1][RG][O];

    const int tid = threadIdx.x;
    const int o = tid % O;
    const int g = tid / O;
    const size_t m0 = (size_t)blockIdx.x * RPB;

    ulonglong2 w[KT4];
    {
        const ulonglong2* wr = (const ulonglong2*)(W + (size_t)o * K + g * KT);
#pragma unroll
        for (int i = 0; i < KT4; i++) w[i] = wr[i];
    }
    const float bias = TWOB ? (bias1[o] + bias2[o]) : bias1[o];

    float4 ld = make_float4(0.f, 0.f, 0.f, 0.f);
    if (tid < NLD) ld = __ldg(((const float4*)(A + m0 * K)) + tid);

    for (int grp = 0; grp < NGR; grp++) {
        const int buf = grp & 1;
        if (tid < NLD) ((float4*)stage[buf])[tid] = ld;
        __syncthreads();
        if (grp + 1 < NGR && tid < NLD)
            ld = __ldg(((const float4*)(A + (m0 + (size_t)(grp + 1) * RG) * K)) + tid);

        float pr[RG];
#pragma unroll
        for (int r = 0; r < RG; r++) {
            const ulonglong2* xr = (const ulonglong2*)(stage[buf] + r * K + g * KT);
            unsigned long long a0 = 0ull, a1 = 0ull;
#pragma unroll
            for (int i = 0; i < KT4; i++) {
                ulonglong2 v = xr[i];
                a0 = fma2(w[i].x, v.x, a0);
                a1 = fma2(w[i].y, v.y, a1);
            }
            pr[r] = red2(a0) + red2(a1);
        }
        if (g) {
#pragma unroll
            for (int r = 0; r < RG; r++) scr[buf][g - 1][r][o] = pr[r];
        }
        __syncthreads();
        if (!g) {
#pragma unroll
            for (int r = 0; r < RG; r++) {
                float s = pr[r] + bias;
#pragma unroll
                for (int q = 0; q < G - 1; q++) s += scr[buf][q][r][o];
                C[(m0 + (size_t)grp * RG + r) * O + o] = s;
            }
        }
    }
}

// =====================================================================
// K2: recurrent scan. Cluster of 2 CTAs per batch (128 CTAs).
// g1 = finisher (R14 structure). NEW: exchange via tagged-slot plain
// DSMEM stores (no mbarrier / async proxy).
//   send @ step t:  st.relaxed.cluster {h, tag=t+1} -> peer pbuf[t&1][jj]
//   recv @ step t:  poll own pbuf[(t-1)&1][jj] until tag==t (t=0: tag 0
//                   pre-initialized), compact to hbuf, bar(3), FMA.
// Tags strictly increase -> no ABA; 8B store is single-copy atomic.
// =====================================================================
__global__ void __cluster_dims__(2, 1, 1) __launch_bounds__(256, 1)
k_scan(const float* __restrict__ w_hh) {
    __shared__ __align__(16) float hbuf[2][HH];
    __shared__ float scr0[2][128];
    __shared__ __align__(16) unsigned long long pbuf[2][128];  // {h, tag} slots

    const int tid = threadIdx.x;
    const int jj = tid & 127;
    const int g = tid >> 7;
    const int rank = blockIdx.x & 1;
    const int b = blockIdx.x >> 1;
    const int j = rank * 128 + jj;
    const int peerbase = (rank ^ 1) * 128;
    const int kbase = g ? peerbase : rank * 128;

    ulonglong2 w[32];
    {
        const ulonglong2* wr = (const ulonglong2*)(w_hh + (size_t)j * HH + kbase);
#pragma unroll
        for (int i = 0; i < 32; i++) w[i] = wr[i];
    }

    for (int i = tid; i < 2 * HH; i += 256) ((float*)hbuf)[i] = 0.0f;
    for (int i = tid; i < 2 * 128; i += 256) ((unsigned long long*)pbuf)[i] = 0ull;
    __syncthreads();
    cluster_sync_();   // peer slots zeroed before any remote store

    const uint32_t peer = rank ^ 1;
    const uint32_t rem_pb0 = mapa_u32(smem_u32(&pbuf[0][jj]), peer);
    const uint32_t rem_pb1 = mapa_u32(smem_u32(&pbuf[1][jj]), peer);
    const uint32_t loc_pb0 = smem_u32(&pbuf[0][jj]);
    const uint32_t loc_pb1 = smem_u32(&pbuf[1][jj]);

    const size_t STRIDE = (size_t)BB * HH;
    const float* xp_ptr = g_xp + (size_t)b * HH + j;
    float* hs_ptr = g_hs + (size_t)b * HH + j;

    // 4-deep xp prefetch ring — held by g1 (the finisher)
    float x0 = 0.f, x1 = 0.f, x2 = 0.f, x3 = 0.f;
    if (g) {
        x0 = __ldg(xp_ptr);
        x1 = __ldg(xp_ptr + STRIDE);
        x2 = __ldg(xp_ptr + 2 * STRIDE);
        x3 = __ldg(xp_ptr + 3 * STRIDE);
        xp_ptr += 4 * STRIDE;
    }

    for (int tt = 0; tt < TT; tt++) {
        const int p = tt & 1;      // write buffer / send slot
        const int rp = p ^ 1;      // read buffer / recv slot

        if (!g) {
            // ---- g0: local-half producer (off the critical chain) ----
            if (tt) nbar_sync(1);   // g1 wrote hbuf[rp] local half (step t-1)
            const ulonglong2* hr = (const ulonglong2*)(&hbuf[rp][kbase]);
            unsigned long long a0 = 0ull, a1 = 0ull, a2 = 0ull, a3 = 0ull;
#pragma unroll
            for (int i = 0; i < 32; i += 2) {
                ulonglong2 v0 = hr[i];
                ulonglong2 v1 = hr[i + 1];
                a0 = fma2(w[i].x, v0.x, a0);
                a1 = fma2(w[i].y, v0.y, a1);
                a2 = fma2(w[i + 1].x, v1.x, a2);
                a3 = fma2(w[i + 1].y, v1.y, a3);
            }
            scr0[p][jj] = (red2(a0) + red2(a1)) + (red2(a2) + red2(a3));
            nbar_arrive(2);         // scr0 ready; also marks hbuf[rp] read done
        } else {
            // ---- g1: peer-half consumer + FINISHER (the critical chain) ----
            float xp_use = x0;      // rotate ring; prefetch issues early
            x0 = x1; x1 = x2; x2 = x3;
            x3 = (tt + 4 < TT) ? __ldg(xp_ptr) : 0.f;
            xp_ptr += STRIDE;

            // receive peer h(t-1): poll own slot (tag == tt; tt=0 pre-init 0)
            float h_own = poll_slot(rp ? loc_pb1 : loc_pb0, (uint32_t)tt);
            hbuf[rp][peerbase + jj] = h_own;   // compact for vectorized FMA
            nbar_sync_g1();                    // all 128 slots compacted

            const ulonglong2* hr = (const ulonglong2*)(&hbuf[rp][kbase]);
            unsigned long long a0 = 0ull, a1 = 0ull, a2 = 0ull, a3 = 0ull;
#pragma unroll
            for (int i = 0; i < 32; i += 2) {
                ulonglong2 v0 = hr[i];
                ulonglong2 v1 = hr[i + 1];
                a0 = fma2(w[i].x, v0.x, a0);
                a1 = fma2(w[i].y, v0.y, a1);
                a2 = fma2(w[i + 1].x, v1.x, a2);
                a3 = fma2(w[i + 1].y, v1.y, a3);
            }
            float part = (red2(a0) + red2(a1)) + (red2(a2) + red2(a3));

            nbar_sync(2);           // g0 arrived long ago -> near-zero wait
            float h = fast_tanh(part + scr0[p][jj] + xp_use);
            st_slot(p ? rem_pb1 : rem_pb0, h, (uint32_t)(tt + 1));  // send
            hbuf[p][j] = h;         // local copy (g0 reads next step)
            *hs_ptr = h;            // HBM stream
            hs_ptr += STRIDE;
            nbar_arrive(1);         // release g0 into step t+1
        }
    }

    cluster_sync_();   // keep smem alive until peer's last stores land
}

// =====================================================================
// Launch sequence: k1(0), nop(1), nop(2), scan(3), k3(4) — keeps the
// ncu capture on k_scan for verification.
// =====================================================================
extern "C" void kernel_launch(void* const* d_in, const int* in_sizes, int n_in,
                              void* d_out, int out_size) {
    const float* x     = (const float*)d_in[0];
    const float* w_ih  = (const float*)d_in[1];
    const float* w_hh  = (const float*)d_in[2];
    const float* b_ih  = (const float*)d_in[3];
    const float* b_hh  = (const float*)d_in[4];
    const float* w_out = (const float*)d_in[5];
    const float* b_out = (const float*)d_in[6];
    float* out = (float*)d_out;

    float *xp, *hs;
    cudaGetSymbolAddress((void**)&xp, g_xp);
    cudaGetSymbolAddress((void**)&hs, g_hs);

    k_proj<HH, NIN, true><<<MROWS / 64, 512>>>(x, w_ih, b_ih, b_hh, xp);
    k_nop<<<1, 32>>>();
    k_nop<<<1, 32>>>();
    k_scan<<<2 * BB, 256>>>(w_hh);
    k_proj<NOUT, HH, false><<<MROWS / 64, 512>>>(hs, w_out, b_out, b_out, out);
}